// round 14
// baseline (speedup 1.0000x reference)
#include <cuda_runtime.h>
#include <cstdint>

#define S 64
#define P 2048
#define C 32
#define A 2048
#define D 128
#define E 64
#define E2 32

#define SPLITS 16
#define PH (P / SPLITS)   // 128 pixels per block
#define SLOTS4 4          // max agent chunks per scene supported (nA<=128; 17-sigma safe)

typedef unsigned long long ull;

__device__ __forceinline__ ull pack2(float lo, float hi) {
    ull r; asm("mov.b64 %0,{%1,%2};" : "=l"(r) : "f"(lo), "f"(hi)); return r;
}
__device__ __forceinline__ void unpack2(ull v, float& lo, float& hi) {
    asm("mov.b64 {%0,%1},%2;" : "=f"(lo), "=f"(hi) : "l"(v));
}
__device__ __forceinline__ ull fma2(ull a, ull b, ull c) {
    ull d; asm("fma.rn.f32x2 %0,%1,%2,%3;" : "=l"(d) : "l"(a), "l"(b), "l"(c)); return d;
}
__device__ __forceinline__ ull add2(ull a, ull b) {
    ull d; asm("add.rn.f32x2 %0,%1,%2;" : "=l"(d) : "l"(a), "l"(b)); return d;
}
__device__ __forceinline__ ull mul2(ull a, ull b) {
    ull d; asm("mul.rn.f32x2 %0,%1,%2;" : "=l"(d) : "l"(a), "l"(b)); return d;
}
__device__ __forceinline__ ull relu2(ull v) {
    float lo, hi; unpack2(v, lo, hi);
    return pack2(fmaxf(lo, 0.f), fmaxf(hi, 0.f));
}

// ------------------------- global scratch -------------------------
__device__ ull   g_att2u[A * E2];
__device__ int   g_alist[S * A];
__device__ int   g_cnt[S];
// per-warp partial softmax states: [scene*SLOTS4+slot][part][kwarp][17][32]
__device__ ull   g_part[(size_t)S * SLOTS4 * SPLITS * 8 * 17 * 32];

// ---------------------------------------------------------------------------
// k_prep: blocks [0,S): per-scene agent lists (2-sync ballot compaction).
//         blocks [S, S+A/32): att2 for 32 agents.
// ---------------------------------------------------------------------------
#define PREP_SMEM 49152
__global__ __launch_bounds__(256) void k_prep(const int* __restrict__ sidx,
                                              const float* __restrict__ dyn,
                                              const float* __restrict__ Wdf,
                                              const float* __restrict__ bdf) {
    extern __shared__ __align__(16) char dsm[];
    __shared__ int cnt8[64];   // [round][warp]

    const int tid = threadIdx.x, wid = tid >> 5, lane = tid & 31;

    if (blockIdx.x < S) {
        // ---- group role ----
        const int s = blockIdx.x;
        unsigned pm = 0;
        int rank[8];
#pragma unroll
        for (int r = 0; r < 8; r++) {
            int a = r * 256 + tid;
            bool p = (sidx[a] == s);
            unsigned bal = __ballot_sync(0xffffffffu, p);
            if (lane == 0) cnt8[r * 8 + wid] = __popc(bal);
            if (p) pm |= (1u << r);
            rank[r] = __popc(bal & ((1u << lane) - 1u));
        }
        __syncthreads();
        int run = 0, off[8];
#pragma unroll
        for (int r = 0; r < 8; r++) {
            int woff = 0, tot = 0;
#pragma unroll
            for (int w = 0; w < 8; w++) {
                int c = cnt8[r * 8 + w];
                if (w < wid) woff += c;
                tot += c;
            }
            off[r] = run + woff;
            run += tot;
        }
#pragma unroll
        for (int r = 0; r < 8; r++)
            if ((pm >> r) & 1)
                g_alist[s * A + off[r] + rank[r]] = r * 256 + tid;
        if (tid == 0) g_cnt[s] = run;
        return;
    }

    // ---- att2 role: 32 agents, 4 per warp ----
    ull*   Wp2   = (ull*)dsm;                 // [128][32] = 32 KB
    float* dyn_s = (float*)(dsm + 32768);     // [32][128] = 16 KB
    const int a0 = (blockIdx.x - S) * 32;
    {
        const ull* Wsrc = (const ull*)Wdf;
#pragma unroll
        for (int k = 0; k < 16; k++) Wp2[tid + k * 256] = Wsrc[tid + k * 256];
        const float4* dsrc = (const float4*)(dyn + (size_t)a0 * D);
        float4* ddst = (float4*)dyn_s;
#pragma unroll
        for (int k = 0; k < 4; k++) ddst[tid + k * 256] = dsrc[tid + k * 256];
    }
    __syncthreads();

    ull acc[4];
    ull b0 = ((const ull*)bdf)[lane];
#pragma unroll
    for (int i = 0; i < 4; i++) acc[i] = b0;
    const float* dr = dyn_s + (wid * 4) * D;
#pragma unroll 4
    for (int c = 0; c < D; c++) {
        ull w2 = Wp2[c * 32 + lane];
#pragma unroll
        for (int i = 0; i < 4; i++) {
            float d = dr[i * D + c];
            acc[i] = fma2(pack2(d, d), w2, acc[i]);
        }
    }
#pragma unroll
    for (int i = 0; i < 4; i++)
        g_att2u[(size_t)(a0 + wid * 4 + i) * E2 + lane] = acc[i];
}

// ---------------------------------------------------------------------------
// k_attn — block = (scene, part). 256 threads / 8 warps, 3 blocks/SM.
// lane = agent (32-agent chunks), warp = 16-pixel slice of 128 pixels.
// NO in-block merge: each warp streams its softmax state to g_part.
// b_fc dropped (softmax-invariant).
// ---------------------------------------------------------------------------
// smem layout (bytes, all 16B aligned)
#define OFF_ATT1S 0                   // ull[128*34] = 34816
#define OFF_GSS   34816               // ull[128*16] = 16384
#define OFF_WP    51200               // ull[32*32]  = 8192
#define OFF_ATT2T 59392               // ull[16*66]  = 8448  (pair-interleaved)
#define OFF_WFC   67840               // ull[32]     = 256
#define OFF_BSN   68096               // ull[32]     = 256
#define SMEM_ATTN 68352

__global__ __launch_bounds__(256, 3) void k_attn(const float* __restrict__ gs,
                                                 const float* __restrict__ wfc,
                                                 const float* __restrict__ Wsn,
                                                 const float* __restrict__ bsn) {
    extern __shared__ __align__(16) char smraw[];
    ull* att1s = (ull*)(smraw + OFF_ATT1S);   // [px][34]
    ull* gss   = (ull*)(smraw + OFF_GSS);     // [px][16]
    ull* Wp    = (ull*)(smraw + OFF_WP);      // [c][32]
    ull* att2T = (ull*)(smraw + OFF_ATT2T);   // [e2pair][66]: per lane 2 ull
    ull* wfcp  = (ull*)(smraw + OFF_WFC);
    ull* bsnp  = (ull*)(smraw + OFF_BSN);

    const int tid = threadIdx.x, wid = tid >> 5, lane = tid & 31;
    const int sblk = blockIdx.x & 63;     // part-major: waves mix scenes
    const int part = blockIdx.x >> 6;
    const int p0 = part * PH;
    const int nA = g_cnt[sblk];
    if (nA == 0) return;

    const int* alist = g_alist + sblk * A;

    // ---- stage weights ----
    {
        const ull* Wsrc = (const ull*)Wsn;
        for (int i = tid; i < C * E2; i += 256) Wp[i] = Wsrc[i];
        if (tid < E2) {
            wfcp[tid] = ((const ull*)wfc)[tid];
            bsnp[tid] = ((const ull*)bsn)[tid];
        }
    }
    __syncthreads();

    // ---- prologue: gs loads in flight, chunk-0 att2 staging, att1 compute --
    {
        const int px = tid >> 1, h16 = (tid & 1) * 16;
        const float4* gr = (const float4*)(gs + (size_t)(sblk * P + p0 + px) * C);
        float4 v4[8];
#pragma unroll
        for (int j = 0; j < 8; j++) v4[j] = gr[j];

        // chunk-0 att2 staging, pair-interleaved layout
        for (int idx = tid; idx < 32 * E2; idx += 256) {
            int j = idx >> 5, e2 = idx & 31;
            int src = j; if (src >= nA) src = nA - 1;
            att2T[(e2 >> 1) * 66 + 2 * j + (e2 & 1)] =
                g_att2u[(size_t)alist[src] * E2 + e2];
        }

        if ((tid & 1) == 0) {
            float4* gd = (float4*)(gss + px * 16);
#pragma unroll
            for (int j = 0; j < 8; j++) gd[j] = v4[j];
        }
        ull acc[16];
#pragma unroll
        for (int k = 0; k < 16; k++) acc[k] = bsnp[h16 + k];
#pragma unroll
        for (int j = 0; j < 8; j++) {
            const float4 v = v4[j];
            {
                ull gg = pack2(v.x, v.x);
                const ull* wr = Wp + (4 * j + 0) * E2 + h16;
#pragma unroll
                for (int k = 0; k < 16; k++) acc[k] = fma2(gg, wr[k], acc[k]);
            }
            {
                ull gg = pack2(v.y, v.y);
                const ull* wr = Wp + (4 * j + 1) * E2 + h16;
#pragma unroll
                for (int k = 0; k < 16; k++) acc[k] = fma2(gg, wr[k], acc[k]);
            }
            {
                ull gg = pack2(v.z, v.z);
                const ull* wr = Wp + (4 * j + 2) * E2 + h16;
#pragma unroll
                for (int k = 0; k < 16; k++) acc[k] = fma2(gg, wr[k], acc[k]);
            }
            {
                ull gg = pack2(v.w, v.w);
                const ull* wr = Wp + (4 * j + 3) * E2 + h16;
#pragma unroll
                for (int k = 0; k < 16; k++) acc[k] = fma2(gg, wr[k], acc[k]);
            }
        }
        ulonglong2* dst = (ulonglong2*)(att1s + px * 34 + h16);
#pragma unroll
        for (int k = 0; k < 8; k++) {
            ulonglong2 v2; v2.x = acc[2 * k]; v2.y = acc[2 * k + 1];
            dst[k] = v2;
        }
    }
    __syncthreads();   // att1s, gss, att2T(chunk 0) visible

    const int pbase = wid * 16;

    for (int c0 = 0; c0 < nA; c0 += 32) {
        if (c0 > 0) {   // restage att2 for this chunk (rare path)
            __syncthreads();   // all warps past previous logit reads
            for (int idx = tid; idx < 32 * E2; idx += 256) {
                int j = idx >> 5, e2 = idx & 31;
                int src = c0 + j; if (src >= nA) src = nA - 1;
                att2T[(e2 >> 1) * 66 + 2 * j + (e2 & 1)] =
                    g_att2u[(size_t)alist[src] * E2 + e2];
            }
            __syncthreads();
        }

        // ---- logits: 16 pixels x 32 lane-agents ----
        ull lg[16];
#pragma unroll
        for (int i = 0; i < 16; i++) lg[i] = 0ull;
#pragma unroll 2
        for (int e2p = 0; e2p < 16; e2p++) {
            ulonglong2 wv2 = *(const ulonglong2*)(wfcp + 2 * e2p);
            ulonglong2 bv2 = *(const ulonglong2*)(att2T + e2p * 66 + 2 * lane);
            const ulonglong2* a1 = (const ulonglong2*)(att1s + pbase * 34 + 2 * e2p);
#pragma unroll
            for (int i = 0; i < 16; i++) {
                ulonglong2 av = a1[i * 17];
                lg[i] = fma2(relu2(add2(av.x, bv2.x)), wv2.x, lg[i]);
                lg[i] = fma2(relu2(add2(av.y, bv2.y)), wv2.y, lg[i]);
            }
        }
        // ---- single-shot softmax over this warp's 16 pixels ----
        float ls[16];
#pragma unroll
        for (int i = 0; i < 16; i++) {
            float lo, hi; unpack2(lg[i], lo, hi);
            ls[i] = lo + hi;
        }
        float t8[8];
#pragma unroll
        for (int i = 0; i < 8; i++) t8[i] = fmaxf(ls[i], ls[i + 8]);
        float m = fmaxf(fmaxf(fmaxf(t8[0], t8[4]), fmaxf(t8[1], t8[5])),
                        fmaxf(fmaxf(t8[2], t8[6]), fmaxf(t8[3], t8[7])));
        float l0 = 0.f, l1 = 0.f;
        ull acc[16];
#pragma unroll
        for (int k = 0; k < 16; k++) acc[k] = 0ull;
#pragma unroll 4
        for (int i = 0; i < 16; i++) {
            float w = __expf(ls[i] - m);
            if (i & 1) l1 += w; else l0 += w;
            ull w2 = pack2(w, w);
            const ulonglong2* grw = (const ulonglong2*)(gss + (pbase + i) * 16);
#pragma unroll
            for (int k = 0; k < 8; k++) {
                ulonglong2 gv = grw[k];
                acc[2 * k]     = fma2(w2, gv.x, acc[2 * k]);
                acc[2 * k + 1] = fma2(w2, gv.y, acc[2 * k + 1]);
            }
        }
        float l = l0 + l1;

        // ---- stream warp state to gmem (coalesced; no barriers) ----
        const int slot = c0 >> 5;
        if (slot < SLOTS4) {
            size_t base = ((((size_t)(sblk * SLOTS4 + slot)) * SPLITS + part) * 8
                           + wid) * 544;
#pragma unroll
            for (int k = 0; k < 16; k++) g_part[base + k * 32 + lane] = acc[k];
            g_part[base + 512 + lane] = pack2(m, l);
        }
    }
}

// ---------------------------------------------------------------------------
// k_comb2 — block per scene: merge 16 parts x 8 kwarps = 128 partial states
// per (slot, lane=agent). Two-pass: coefs first (indep LDGs), then fma sums.
// ---------------------------------------------------------------------------
__global__ __launch_bounds__(256) void k_comb2(float* __restrict__ out) {
    __shared__ ull   pbuf[8][544];    // 34816 B: per-warp merged partials
    __shared__ float cf[8][32];       // final merge coefs
    __shared__ float Lb[32];

    const int tid = threadIdx.x, wid = tid >> 5, lane = tid & 31;
    const int sblk = blockIdx.x;
    const int nA = g_cnt[sblk];
    if (nA == 0) return;
    const int* alist = g_alist + sblk * A;
    int nslot = (nA + 31) >> 5; if (nslot > SLOTS4) nslot = SLOTS4;

    for (int slot = 0; slot < nslot; slot++) {
        // warp wid merges 16 states: parts [2wid, 2wid+2) x kwarps [0,8)
        const size_t base0 = (((size_t)(sblk * SLOTS4 + slot)) * SPLITS * 8
                              + (size_t)wid * 16) * 544;
        // pass 1: (m,l) of all 16 states -> coefs
        float mj[16], lj[16];
#pragma unroll
        for (int t = 0; t < 16; t++)
            unpack2(g_part[base0 + (size_t)t * 544 + 512 + lane], mj[t], lj[t]);
        float M = mj[0];
#pragma unroll
        for (int t = 1; t < 16; t++) M = fmaxf(M, mj[t]);
        float L = 0.f;
        ull c2[16];
#pragma unroll
        for (int t = 0; t < 16; t++) {
            float c = __expf(mj[t] - M);
            L += lj[t] * c;
            c2[t] = pack2(c, c);
        }
        // pass 2: weighted sums per k (independent LDG streams)
#pragma unroll 2
        for (int k = 0; k < 16; k++) {
            ull s = 0ull;
#pragma unroll
            for (int t = 0; t < 16; t++)
                s = fma2(g_part[base0 + (size_t)t * 544 + k * 32 + lane], c2[t], s);
            pbuf[wid][k * 32 + lane] = s;
        }
        pbuf[wid][512 + lane] = pack2(M, L);
        __syncthreads();

        if (wid == 0) {
            float m8[8], l8[8];
#pragma unroll
            for (int j = 0; j < 8; j++)
                unpack2(pbuf[j][512 + lane], m8[j], l8[j]);
            float MM = m8[0];
#pragma unroll
            for (int j = 1; j < 8; j++) MM = fmaxf(MM, m8[j]);
            float LL = 0.f;
#pragma unroll
            for (int j = 0; j < 8; j++) {
                float cj = __expf(m8[j] - MM);
                cf[j][lane] = cj;
                LL += l8[j] * cj;
            }
            Lb[lane] = LL;
        }
        __syncthreads();

        const int aidx = slot * 32 + lane;
        if (aidx < nA) {
            const int k0 = wid * 2;
            ull s0 = 0ull, s1 = 0ull;
#pragma unroll
            for (int j = 0; j < 8; j++) {
                float cj = cf[j][lane];
                ull cc = pack2(cj, cj);
                s0 = fma2(pbuf[j][k0 * 32 + lane], cc, s0);
                s1 = fma2(pbuf[j][(k0 + 1) * 32 + lane], cc, s1);
            }
            float inv = 1.0f / Lb[lane];
            float a0, a1, a2, a3;
            unpack2(s0, a0, a1);
            unpack2(s1, a2, a3);
            int a = alist[aidx];
            float4 o; o.x = a0 * inv; o.y = a1 * inv; o.z = a2 * inv; o.w = a3 * inv;
            *(float4*)(out + (size_t)a * C + wid * 4) = o;
        }
        __syncthreads();   // pbuf/cf reuse next slot
    }
}

// ---------------------------------------------------------------------------
extern "C" void kernel_launch(void* const* d_in, const int* in_sizes, int n_in,
                              void* d_out, int out_size) {
    const float* gs   = (const float*)d_in[0];
    const int*   sidx = (const int*)d_in[1];
    const float* dyn  = (const float*)d_in[2];
    const float* Wsn  = (const float*)d_in[3];
    const float* bsn  = (const float*)d_in[4];
    const float* Wdf  = (const float*)d_in[5];
    const float* bdf  = (const float*)d_in[6];
    const float* wfc  = (const float*)d_in[7];
    float* out = (float*)d_out;

    cudaFuncSetAttribute(k_prep, cudaFuncAttributeMaxDynamicSharedMemorySize,
                         PREP_SMEM);
    k_prep<<<S + A / 32, 256, PREP_SMEM>>>(sidx, dyn, Wdf, bdf);

    cudaFuncSetAttribute(k_attn, cudaFuncAttributeMaxDynamicSharedMemorySize,
                         SMEM_ATTN);
    k_attn<<<S * SPLITS, 256, SMEM_ATTN>>>(gs, wfc, Wsn, bsn);

    k_comb2<<<S, 256>>>(out);
}

// round 15
// speedup vs baseline: 1.3896x; 1.3896x over previous
#include <cuda_runtime.h>
#include <cstdint>

#define S 64
#define P 2048
#define C 32
#define A 2048
#define D 128
#define E 64
#define E2 32

#define SPLITS 16
#define PH (P / SPLITS)   // 128 pixels per block

typedef unsigned long long ull;

__device__ __forceinline__ ull pack2(float lo, float hi) {
    ull r; asm("mov.b64 %0,{%1,%2};" : "=l"(r) : "f"(lo), "f"(hi)); return r;
}
__device__ __forceinline__ void unpack2(ull v, float& lo, float& hi) {
    asm("mov.b64 {%0,%1},%2;" : "=f"(lo), "=f"(hi) : "l"(v));
}
__device__ __forceinline__ ull fma2(ull a, ull b, ull c) {
    ull d; asm("fma.rn.f32x2 %0,%1,%2,%3;" : "=l"(d) : "l"(a), "l"(b), "l"(c)); return d;
}
__device__ __forceinline__ ull add2(ull a, ull b) {
    ull d; asm("add.rn.f32x2 %0,%1,%2;" : "=l"(d) : "l"(a), "l"(b)); return d;
}
__device__ __forceinline__ ull mul2(ull a, ull b) {
    ull d; asm("mul.rn.f32x2 %0,%1,%2;" : "=l"(d) : "l"(a), "l"(b)); return d;
}
__device__ __forceinline__ ull relu2(ull v) {
    float lo, hi; unpack2(v, lo, hi);
    return pack2(fmaxf(lo, 0.f), fmaxf(hi, 0.f));
}
__device__ __forceinline__ void pdl_trigger() {
    asm volatile("griddepcontrol.launch_dependents;" ::: "memory");
}
__device__ __forceinline__ void pdl_wait() {
    asm volatile("griddepcontrol.wait;" ::: "memory");
}

// ------------------------- global scratch -------------------------
__device__ ull   g_att2u[A * E2];
__device__ int   g_alist[S * A];
__device__ int   g_cnt[S];
__device__ float g_pm[A * SPLITS];
__device__ float g_pl[A * SPLITS];
__device__ ull   g_paccu[A * SPLITS * (C / 2)];

// ---------------------------------------------------------------------------
// k_prep: blocks [0,S): per-scene agent lists (2-sync ballot compaction).
//         blocks [S, S+A/32): att2 for 32 agents.
// Each block: writes -> __syncthreads -> __threadfence -> PDL trigger.
// ---------------------------------------------------------------------------
#define PREP_SMEM 49152
__global__ __launch_bounds__(256) void k_prep(const int* __restrict__ sidx,
                                              const float* __restrict__ dyn,
                                              const float* __restrict__ Wdf,
                                              const float* __restrict__ bdf) {
    extern __shared__ __align__(16) char dsm[];
    __shared__ int cnt8[64];   // [round][warp]

    const int tid = threadIdx.x, wid = tid >> 5, lane = tid & 31;

    if (blockIdx.x < S) {
        // ---- group role ----
        const int s = blockIdx.x;
        unsigned pm = 0;
        int rank[8];
#pragma unroll
        for (int r = 0; r < 8; r++) {
            int a = r * 256 + tid;
            bool p = (sidx[a] == s);
            unsigned bal = __ballot_sync(0xffffffffu, p);
            if (lane == 0) cnt8[r * 8 + wid] = __popc(bal);
            if (p) pm |= (1u << r);
            rank[r] = __popc(bal & ((1u << lane) - 1u));
        }
        __syncthreads();
        int run = 0, off[8];
#pragma unroll
        for (int r = 0; r < 8; r++) {
            int woff = 0, tot = 0;
#pragma unroll
            for (int w = 0; w < 8; w++) {
                int c = cnt8[r * 8 + w];
                if (w < wid) woff += c;
                tot += c;
            }
            off[r] = run + woff;
            run += tot;
        }
#pragma unroll
        for (int r = 0; r < 8; r++)
            if ((pm >> r) & 1)
                g_alist[s * A + off[r] + rank[r]] = r * 256 + tid;
        if (tid == 0) g_cnt[s] = run;
        __syncthreads();
        if (tid == 0) { __threadfence(); pdl_trigger(); }
        return;
    }

    // ---- att2 role: 32 agents, 4 per warp ----
    ull*   Wp2   = (ull*)dsm;                 // [128][32] = 32 KB
    float* dyn_s = (float*)(dsm + 32768);     // [32][128] = 16 KB
    const int a0 = (blockIdx.x - S) * 32;
    {
        const ull* Wsrc = (const ull*)Wdf;
#pragma unroll
        for (int k = 0; k < 16; k++) Wp2[tid + k * 256] = Wsrc[tid + k * 256];
        const float4* dsrc = (const float4*)(dyn + (size_t)a0 * D);
        float4* ddst = (float4*)dyn_s;
#pragma unroll
        for (int k = 0; k < 4; k++) ddst[tid + k * 256] = dsrc[tid + k * 256];
    }
    __syncthreads();

    ull acc[4];
    ull b0 = ((const ull*)bdf)[lane];
#pragma unroll
    for (int i = 0; i < 4; i++) acc[i] = b0;
    const float* dr = dyn_s + (wid * 4) * D;
#pragma unroll 4
    for (int c = 0; c < D; c++) {
        ull w2 = Wp2[c * 32 + lane];
#pragma unroll
        for (int i = 0; i < 4; i++) {
            float d = dr[i * D + c];
            acc[i] = fma2(pack2(d, d), w2, acc[i]);
        }
    }
#pragma unroll
    for (int i = 0; i < 4; i++)
        g_att2u[(size_t)(a0 + wid * 4 + i) * E2 + lane] = acc[i];
    __syncthreads();
    if (tid == 0) { __threadfence(); pdl_trigger(); }
}

// ---------------------------------------------------------------------------
// k_attn — block = (scene, part). 256 threads / 8 warps, 3 blocks/SM.
// lane = agent (32-agent chunks), warp = 16-pixel slice of 128 pixels.
// Weight staging (inputs) before griddepcontrol.wait; prep outputs after.
// Merge buffer overlays Wp+att2T. b_fc dropped (softmax-invariant).
// ---------------------------------------------------------------------------
// smem layout (bytes)
#define OFF_ATT1S 0                   // ull[128*34] = 34816
#define OFF_GSS   34816               // ull[128*16] = 16384
#define OFF_OVR   51200               // overlay region, 17408 bytes:
                                      //   Wp    @ +0     (ull[32*32] = 8192)
                                      //   att2T @ +8192  (ull[16*66] = 8448, pair-interleaved)
                                      //   mbuf  @ +0     (ull[4*17*32] = 17408)
#define OFF_COEF  68608               // float[4*32] = 512
#define OFF_WFC   69120               // ull[32] = 256
#define OFF_BSN   69376               // ull[32] = 256
#define SMEM_ATTN 69632

__global__ __launch_bounds__(256, 3) void k_attn(const float* __restrict__ gs,
                                                 const float* __restrict__ wfc,
                                                 const float* __restrict__ Wsn,
                                                 const float* __restrict__ bsn) {
    extern __shared__ __align__(16) char smraw[];
    ull*   att1s = (ull*)(smraw + OFF_ATT1S);        // [px][34]
    ull*   gss   = (ull*)(smraw + OFF_GSS);          // [px][16]
    ull*   Wp    = (ull*)(smraw + OFF_OVR);          // [c][32] (prologue only)
    ull*   att2T = (ull*)(smraw + OFF_OVR + 8192);   // [e2pair][66] (logit phase)
    ull*   mbuf  = (ull*)(smraw + OFF_OVR);          // [4][17][32] (merge phase)
    float* coef  = (float*)(smraw + OFF_COEF);       // [4][32]
    ull*   wfcp  = (ull*)(smraw + OFF_WFC);
    ull*   bsnp  = (ull*)(smraw + OFF_BSN);

    const int tid = threadIdx.x, wid = tid >> 5, lane = tid & 31;
    const int sblk = blockIdx.x & 63;     // part-major: waves mix scenes
    const int part = blockIdx.x >> 6;
    const int p0 = part * PH;

    // ---- stage weights (pure inputs — legal before PDL wait) ----
    {
        const ull* Wsrc = (const ull*)Wsn;
        for (int i = tid; i < C * E2; i += 256) Wp[i] = Wsrc[i];
        if (tid < E2) {
            wfcp[tid] = ((const ull*)wfc)[tid];
            bsnp[tid] = ((const ull*)bsn)[tid];
        }
    }
    pdl_wait();        // k_prep outputs (g_cnt, g_alist, g_att2u) now valid
    const int nA = g_cnt[sblk];
    if (nA == 0) return;
    const int* alist = g_alist + sblk * A;
    __syncthreads();   // weights visible

    // ---- prologue: gs loads in flight, chunk-0 att2 staging, att1 compute --
    {
        const int px = tid >> 1, h16 = (tid & 1) * 16;
        const float4* gr = (const float4*)(gs + (size_t)(sblk * P + p0 + px) * C);
        float4 v4[8];
#pragma unroll
        for (int j = 0; j < 8; j++) v4[j] = gr[j];

        // chunk-0 att2 staging, pair-interleaved (LDG latency overlaps below)
        for (int idx = tid; idx < 32 * E2; idx += 256) {
            int j = idx >> 5, e2 = idx & 31;
            int src = j; if (src >= nA) src = nA - 1;
            att2T[(e2 >> 1) * 66 + 2 * j + (e2 & 1)] =
                g_att2u[(size_t)alist[src] * E2 + e2];
        }

        if ((tid & 1) == 0) {
            float4* gd = (float4*)(gss + px * 16);
#pragma unroll
            for (int j = 0; j < 8; j++) gd[j] = v4[j];
        }
        ull acc[16];
#pragma unroll
        for (int k = 0; k < 16; k++) acc[k] = bsnp[h16 + k];
#pragma unroll
        for (int j = 0; j < 8; j++) {
            const float4 v = v4[j];
            {
                ull gg = pack2(v.x, v.x);
                const ull* wr = Wp + (4 * j + 0) * E2 + h16;
#pragma unroll
                for (int k = 0; k < 16; k++) acc[k] = fma2(gg, wr[k], acc[k]);
            }
            {
                ull gg = pack2(v.y, v.y);
                const ull* wr = Wp + (4 * j + 1) * E2 + h16;
#pragma unroll
                for (int k = 0; k < 16; k++) acc[k] = fma2(gg, wr[k], acc[k]);
            }
            {
                ull gg = pack2(v.z, v.z);
                const ull* wr = Wp + (4 * j + 2) * E2 + h16;
#pragma unroll
                for (int k = 0; k < 16; k++) acc[k] = fma2(gg, wr[k], acc[k]);
            }
            {
                ull gg = pack2(v.w, v.w);
                const ull* wr = Wp + (4 * j + 3) * E2 + h16;
#pragma unroll
                for (int k = 0; k < 16; k++) acc[k] = fma2(gg, wr[k], acc[k]);
            }
        }
        ulonglong2* dst = (ulonglong2*)(att1s + px * 34 + h16);
#pragma unroll
        for (int k = 0; k < 8; k++) {
            ulonglong2 v2; v2.x = acc[2 * k]; v2.y = acc[2 * k + 1];
            dst[k] = v2;
        }
    }
    __syncthreads();   // att1s, gss, att2T(chunk 0) visible

    const int pbase = wid * 16;

    for (int c0 = 0; c0 < nA; c0 += 32) {
        // ---- logits: 16 pixels x 32 lane-agents ----
        ull lg[16];
#pragma unroll
        for (int i = 0; i < 16; i++) lg[i] = 0ull;
#pragma unroll 4
        for (int e2p = 0; e2p < 16; e2p++) {
            ulonglong2 wv2 = *(const ulonglong2*)(wfcp + 2 * e2p);
            ulonglong2 bv2 = *(const ulonglong2*)(att2T + e2p * 66 + 2 * lane);
            const ulonglong2* a1 = (const ulonglong2*)(att1s + pbase * 34 + 2 * e2p);
#pragma unroll
            for (int i = 0; i < 16; i++) {
                ulonglong2 av = a1[i * 17];
                lg[i] = fma2(relu2(add2(av.x, bv2.x)), wv2.x, lg[i]);
                lg[i] = fma2(relu2(add2(av.y, bv2.y)), wv2.y, lg[i]);
            }
        }
        // ---- single-shot softmax over this warp's 16 pixels ----
        float ls[16];
#pragma unroll
        for (int i = 0; i < 16; i++) {
            float lo, hi; unpack2(lg[i], lo, hi);
            ls[i] = lo + hi;
        }
        float t8[8];
#pragma unroll
        for (int i = 0; i < 8; i++) t8[i] = fmaxf(ls[i], ls[i + 8]);
        float m = fmaxf(fmaxf(fmaxf(t8[0], t8[4]), fmaxf(t8[1], t8[5])),
                        fmaxf(fmaxf(t8[2], t8[6]), fmaxf(t8[3], t8[7])));
        float l0 = 0.f, l1 = 0.f;
        ull acc[16];
#pragma unroll
        for (int k = 0; k < 16; k++) acc[k] = 0ull;
#pragma unroll 4
        for (int i = 0; i < 16; i++) {
            float w = __expf(ls[i] - m);
            if (i & 1) l1 += w; else l0 += w;
            ull w2 = pack2(w, w);
            const ulonglong2* grw = (const ulonglong2*)(gss + (pbase + i) * 16);
#pragma unroll
            for (int k = 0; k < 8; k++) {
                ulonglong2 gv = grw[k];
                acc[2 * k]     = fma2(w2, gv.x, acc[2 * k]);
                acc[2 * k + 1] = fma2(w2, gv.y, acc[2 * k + 1]);
            }
        }
        float l = l0 + l1;

        __syncthreads();   // (B) logit/V done -> overlay region reusable

        // ---- warps 4-7 dump into slots 0-3 ----
        if (wid >= 4) {
            ull* dst = mbuf + (size_t)(wid - 4) * 17 * 32;
#pragma unroll
            for (int k = 0; k < 16; k++) dst[k * 32 + lane] = acc[k];
            dst[16 * 32 + lane] = pack2(m, l);
        }
        __syncthreads();   // (C)

        // ---- warps 0-3: fold partner state into registers, write back ----
        if (wid < 4) {
            ull* sl = mbuf + (size_t)wid * 17 * 32;
            float m2, l2; unpack2(sl[16 * 32 + lane], m2, l2);
            float Mn = fmaxf(m, m2);
            float s1 = __expf(m - Mn), s2 = __expf(m2 - Mn);
            l = l * s1 + l2 * s2;
            ull s1v = pack2(s1, s1), s2v = pack2(s2, s2);
#pragma unroll
            for (int k = 0; k < 16; k++) {
                acc[k] = fma2(sl[k * 32 + lane], s2v, mul2(acc[k], s1v));
                sl[k * 32 + lane] = acc[k];
            }
            sl[16 * 32 + lane] = pack2(Mn, l);
        }
        __syncthreads();   // (D)

        const int aidx = c0 + lane;
        const bool valid = (aidx < nA);

        if (wid == 0) {
            float mj[4], lj[4];
#pragma unroll
            for (int j = 0; j < 4; j++)
                unpack2(mbuf[(size_t)j * 17 * 32 + 16 * 32 + lane], mj[j], lj[j]);
            float M = fmaxf(fmaxf(mj[0], mj[1]), fmaxf(mj[2], mj[3]));
            float L = 0.f;
#pragma unroll
            for (int j = 0; j < 4; j++) {
                float cj = __expf(mj[j] - M);
                coef[j * 32 + lane] = cj;
                L += lj[j] * cj;
            }
            if (valid) {
                int a = alist[aidx];
                g_pm[(size_t)a * SPLITS + part] = M;
                g_pl[(size_t)a * SPLITS + part] = L;
            }
        }
        __syncthreads();   // (E) coefs visible

        // ---- all 8 warps: weighted k-sums over 4 merged states ----
        {
            const int k0 = wid * 2;
            ull s0 = 0ull, s1 = 0ull;
#pragma unroll
            for (int j = 0; j < 4; j++) {
                float cj = coef[j * 32 + lane];
                ull c2 = pack2(cj, cj);
                const ull* src = mbuf + (size_t)j * 17 * 32;
                s0 = fma2(src[k0 * 32 + lane], c2, s0);
                s1 = fma2(src[(k0 + 1) * 32 + lane], c2, s1);
            }
            if (valid) {
                int a = alist[aidx];
                size_t base = ((size_t)a * SPLITS + part) * 16;
                g_paccu[base + k0] = s0;
                g_paccu[base + k0 + 1] = s1;
            }
        }

        // ---- restage att2 (pair-interleaved) for next chunk (rare) ----
        if (c0 + 32 < nA) {
            __syncthreads();   // ksum readers done with mbuf
            for (int idx = tid; idx < 32 * E2; idx += 256) {
                int j = idx >> 5, e2 = idx & 31;
                int src = c0 + 32 + j; if (src >= nA) src = nA - 1;
                att2T[(e2 >> 1) * 66 + 2 * j + (e2 & 1)] =
                    g_att2u[(size_t)alist[src] * E2 + e2];
            }
            __syncthreads();   // att2T visible for next iteration
        }
    }
}

// ---------------------------------------------------------------------------
// combine SPLITS partial softmax states per agent
// ---------------------------------------------------------------------------
__global__ __launch_bounds__(256) void k_combine(float* __restrict__ out) {
    int gw = (blockIdx.x * blockDim.x + threadIdx.x) >> 5;
    int lane = threadIdx.x & 31;
    if (gw >= A) return;
    int a = gw;
    float mm[SPLITS], llv[SPLITS];
    float M = -1e30f;
#pragma unroll
    for (int k = 0; k < SPLITS; k++) {
        mm[k] = g_pm[a * SPLITS + k];
        llv[k] = g_pl[a * SPLITS + k];
        M = fmaxf(M, mm[k]);
    }
    const float* gp = (const float*)g_paccu;
    float L = 0.f, v = 0.f;
#pragma unroll
    for (int k = 0; k < SPLITS; k++) {
        float sk = __expf(mm[k] - M);
        L += llv[k] * sk;
        v += gp[(size_t)(a * SPLITS + k) * C + lane] * sk;
    }
    out[a * C + lane] = v / L;
}

// ---------------------------------------------------------------------------
extern "C" void kernel_launch(void* const* d_in, const int* in_sizes, int n_in,
                              void* d_out, int out_size) {
    const float* gs   = (const float*)d_in[0];
    const int*   sidx = (const int*)d_in[1];
    const float* dyn  = (const float*)d_in[2];
    const float* Wsn  = (const float*)d_in[3];
    const float* bsn  = (const float*)d_in[4];
    const float* Wdf  = (const float*)d_in[5];
    const float* bdf  = (const float*)d_in[6];
    const float* wfc  = (const float*)d_in[7];
    float* out = (float*)d_out;

    cudaFuncSetAttribute(k_prep, cudaFuncAttributeMaxDynamicSharedMemorySize,
                         PREP_SMEM);
    k_prep<<<S + A / 32, 256, PREP_SMEM>>>(sidx, dyn, Wdf, bdf);

    cudaFuncSetAttribute(k_attn, cudaFuncAttributeMaxDynamicSharedMemorySize,
                         SMEM_ATTN);
    {
        cudaLaunchConfig_t cfg = {};
        cfg.gridDim = dim3(S * SPLITS, 1, 1);
        cfg.blockDim = dim3(256, 1, 1);
        cfg.dynamicSmemBytes = SMEM_ATTN;
        cfg.stream = 0;
        cudaLaunchAttribute attr[1];
        attr[0].id = cudaLaunchAttributeProgrammaticStreamSerialization;
        attr[0].val.programmaticStreamSerializationAllowed = 1;
        cfg.attrs = attr;
        cfg.numAttrs = 1;
        cudaLaunchKernelEx(&cfg, k_attn, gs, wfc, Wsn, bsn);
    }

    k_combine<<<(A * 32) / 256, 256>>>(out);
}